// round 3
// baseline (speedup 1.0000x reference)
#include <cuda_runtime.h>
#include <cuda_bf16.h>
#include <math.h>

// ---------------------------------------------------------------------------
// Problem constants (fixed by dataset)
// ---------------------------------------------------------------------------
#define BB   16
#define NN   1024
#define HH   256
#define FF   400
#define NH   4
#define DH   64
#define NACC 512
#define NREJ 256
#define NFRD 256

// ---------------------------------------------------------------------------
// Static scratch (no allocation allowed). ~127 MB total.
// g_ff doubles as ctx storage (live ranges disjoint; FF >= HH).
// ---------------------------------------------------------------------------
__device__ float g_bufA[BB * NN * HH];        // 16.8 MB
__device__ float g_bufB[BB * NN * HH];        // 16.8 MB
__device__ float g_bufT[BB * NN * HH];        // 16.8 MB (H-wide temps only)
__device__ float g_qkv [BB * NN * 3 * HH];    // 50 MB
__device__ float g_ff  [BB * NN * FF];        // 26 MB (also holds ctx)
__device__ float g_means[BB * 3 * HH];

// ---------------------------------------------------------------------------
// Gather: h0[b,n,:] = emb_table[idx[b,n], :]   (vectorized float4)
// ---------------------------------------------------------------------------
__global__ void gather_kernel(const int* __restrict__ idx,
                              const float* __restrict__ table,
                              float* __restrict__ out)
{
    size_t i = (size_t)blockIdx.x * blockDim.x + threadIdx.x;  // rows * 64
    if (i >= (size_t)BB * NN * (HH / 4)) return;
    size_t row = i >> 6;           // HH/4 = 64 float4 per row
    int    e4  = (int)(i & 63);
    int    id  = idx[row];
    reinterpret_cast<float4*>(out)[row * 64 + e4] =
        reinterpret_cast<const float4*>(table)[(size_t)id * 64 + e4];
}

// ---------------------------------------------------------------------------
// Generic batched GEMM:  C[z] = A[z] (MxK) @ B[z] (KxN) [+ bias] [relu]
// Row-major contiguous. 64x64x16 tiles, 16x16 threads, 4x4 per thread.
// ---------------------------------------------------------------------------
__global__ void gemm_bias_kernel(const float* __restrict__ A,
                                 const float* __restrict__ B,
                                 const float* __restrict__ bias,
                                 float* __restrict__ C,
                                 int M, int N, int K,
                                 size_t sA, size_t sB, size_t sC,
                                 int relu)
{
    A += (size_t)blockIdx.z * sA;
    B += (size_t)blockIdx.z * sB;
    C += (size_t)blockIdx.z * sC;

    __shared__ float As[16][65];   // [k][m]
    __shared__ float Bs[16][65];   // [k][n]

    const int tx = threadIdx.x, ty = threadIdx.y;
    const int tid = ty * 16 + tx;
    const int m0 = blockIdx.y * 64;
    const int n0 = blockIdx.x * 64;

    float acc[4][4] = {};

    for (int k0 = 0; k0 < K; k0 += 16) {
        #pragma unroll
        for (int r = 0; r < 4; r++) {
            int idx = r * 256 + tid;
            int m = idx >> 4, kk = idx & 15;
            float v = 0.f;
            if (m0 + m < M && k0 + kk < K)
                v = A[(size_t)(m0 + m) * K + k0 + kk];
            As[kk][m] = v;
        }
        #pragma unroll
        for (int r = 0; r < 4; r++) {
            int idx = r * 256 + tid;
            int kk = idx >> 6, n = idx & 63;
            float v = 0.f;
            if (k0 + kk < K && n0 + n < N)
                v = B[(size_t)(k0 + kk) * N + n0 + n];
            Bs[kk][n] = v;
        }
        __syncthreads();
        #pragma unroll
        for (int kk = 0; kk < 16; kk++) {
            float a[4], b[4];
            #pragma unroll
            for (int i = 0; i < 4; i++) a[i] = As[kk][ty * 4 + i];
            #pragma unroll
            for (int j = 0; j < 4; j++) b[j] = Bs[kk][tx * 4 + j];
            #pragma unroll
            for (int i = 0; i < 4; i++)
                #pragma unroll
                for (int j = 0; j < 4; j++)
                    acc[i][j] += a[i] * b[j];
        }
        __syncthreads();
    }

    #pragma unroll
    for (int i = 0; i < 4; i++) {
        int m = m0 + ty * 4 + i;
        if (m >= M) continue;
        #pragma unroll
        for (int j = 0; j < 4; j++) {
            int n = n0 + tx * 4 + j;
            if (n >= N) continue;
            float v = acc[i][j];
            if (bias) v += bias[n];
            if (relu) v = fmaxf(v, 0.f);
            C[(size_t)m * N + n] = v;
        }
    }
}

// ---------------------------------------------------------------------------
// Flash-style attention for one block-diagonal segment.
// Block = (qtile64, head, batch), 16x16 threads, 4x4 per thread.
// Static smem = exactly 48 KB: sQ (Q, row-major), sKP (K swizzled-transposed,
// then reused for P), sV (V row-major). Online softmax, no opt-in smem.
// qkv layout: [B, N, 768]; q at +0, k at +256, v at +512, head h at +h*64.
// ---------------------------------------------------------------------------
__global__ void attn_kernel(const float* __restrict__ qkv,
                            float* __restrict__ ctx,
                            int seg_start, int S)
{
    __shared__ float sQ [64 * 64];
    __shared__ float sKP[64 * 64];
    __shared__ float sV [64 * 64];

    const int h  = blockIdx.y;
    const int b  = blockIdx.z;
    const int q0 = blockIdx.x * 64;
    const int tx = threadIdx.x, ty = threadIdx.y;
    const int tid = ty * 16 + tx;

    const size_t rowbase = ((size_t)b * NN + seg_start) * (3 * HH);

    // Q tile row-major, float4 (gmem offset h*64 is 16B aligned)
    #pragma unroll
    for (int r = 0; r < 4; r++) {
        int idx = r * 256 + tid;          // over 1024 float4
        int i = idx >> 4, d4 = idx & 15;
        float4 v = *reinterpret_cast<const float4*>(
            &qkv[rowbase + (size_t)(q0 + i) * (3 * HH) + h * DH + d4 * 4]);
        *reinterpret_cast<float4*>(&sQ[i * 64 + d4 * 4]) = v;
    }

    float run_max[4], run_sum[4], o[4][4];
    #pragma unroll
    for (int i = 0; i < 4; i++) {
        run_max[i] = -1e30f; run_sum[i] = 0.f;
        #pragma unroll
        for (int d = 0; d < 4; d++) o[i][d] = 0.f;
    }

    __syncthreads();

    for (int kt = 0; kt < S; kt += 64) {
        // K tile, transposed + XOR-swizzled: element (j,d) -> sKP[d*64 + (j^d)]
        #pragma unroll
        for (int r = 0; r < 4; r++) {
            int idx = r * 256 + tid;
            int j = idx >> 4, d4 = idx & 15;
            float4 v = *reinterpret_cast<const float4*>(
                &qkv[rowbase + (size_t)(kt + j) * (3 * HH) + HH + h * DH + d4 * 4]);
            int d0 = d4 * 4;
            sKP[(d0 + 0) * 64 + (j ^ (d0 + 0))] = v.x;
            sKP[(d0 + 1) * 64 + (j ^ (d0 + 1))] = v.y;
            sKP[(d0 + 2) * 64 + (j ^ (d0 + 2))] = v.z;
            sKP[(d0 + 3) * 64 + (j ^ (d0 + 3))] = v.w;
        }
        __syncthreads();

        // S = Q K^T  (vectorized LDS.128 on both operands)
        float acc[4][4] = {};
        #pragma unroll 4
        for (int dd = 0; dd < 16; dd++) {
            float4 a4[4];
            #pragma unroll
            for (int i = 0; i < 4; i++)
                a4[i] = *reinterpret_cast<const float4*>(
                    &sQ[(ty * 4 + i) * 64 + dd * 4]);
            #pragma unroll
            for (int c = 0; c < 4; c++) {
                const int d = dd * 4 + c;
                // cols (tx*4+j)^d form one aligned float4 at (tx*4)^(d&60),
                // with component j stored at position j^c.
                float4 b4 = *reinterpret_cast<const float4*>(
                    &sKP[d * 64 + ((tx * 4) ^ (d & 60))]);
                float bv[4];
                ((float*)&bv)[0 ^ c] = b4.x;
                ((float*)&bv)[1 ^ c] = b4.y;
                ((float*)&bv)[2 ^ c] = b4.z;
                ((float*)&bv)[3 ^ c] = b4.w;
                float av[4] = { ((const float*)&a4[0])[c],
                                ((const float*)&a4[1])[c],
                                ((const float*)&a4[2])[c],
                                ((const float*)&a4[3])[c] };
                #pragma unroll
                for (int i = 0; i < 4; i++)
                    #pragma unroll
                    for (int j = 0; j < 4; j++)
                        acc[i][j] += av[i] * bv[j];
            }
        }
        __syncthreads();   // K reads done; sKP will be overwritten with P

        // online softmax update (row groups = 16 lanes sharing ty)
        #pragma unroll
        for (int i = 0; i < 4; i++) {
            float tmax = -1e30f;
            #pragma unroll
            for (int j = 0; j < 4; j++) {
                acc[i][j] *= 0.125f;
                tmax = fmaxf(tmax, acc[i][j]);
            }
            #pragma unroll
            for (int off = 8; off; off >>= 1)
                tmax = fmaxf(tmax, __shfl_xor_sync(0xffffffffu, tmax, off, 16));
            float nm = fmaxf(run_max[i], tmax);
            float f  = __expf(run_max[i] - nm);
            float ts = 0.f;
            #pragma unroll
            for (int j = 0; j < 4; j++) {
                acc[i][j] = __expf(acc[i][j] - nm);
                ts += acc[i][j];
            }
            #pragma unroll
            for (int off = 8; off; off >>= 1)
                ts += __shfl_xor_sync(0xffffffffu, ts, off, 16);
            run_sum[i] = run_sum[i] * f + ts;
            run_max[i] = nm;
            #pragma unroll
            for (int d = 0; d < 4; d++) o[i][d] *= f;
            #pragma unroll
            for (int j = 0; j < 4; j++)
                sKP[(ty * 4 + i) * 64 + tx * 4 + j] = acc[i][j];
        }

        // V tile row-major, float4
        #pragma unroll
        for (int r = 0; r < 4; r++) {
            int idx = r * 256 + tid;
            int j = idx >> 4, d4 = idx & 15;
            float4 v = *reinterpret_cast<const float4*>(
                &qkv[rowbase + (size_t)(kt + j) * (3 * HH) + 2 * HH + h * DH + d4 * 4]);
            *reinterpret_cast<float4*>(&sV[j * 64 + d4 * 4]) = v;
        }
        __syncthreads();

        // O += P @ V
        #pragma unroll 4
        for (int j = 0; j < 64; j++) {
            float p[4];
            #pragma unroll
            for (int i = 0; i < 4; i++) p[i] = sKP[(ty * 4 + i) * 64 + j];
            float4 v4 = *reinterpret_cast<const float4*>(&sV[j * 64 + tx * 4]);
            const float* v = (const float*)&v4;
            #pragma unroll
            for (int i = 0; i < 4; i++)
                #pragma unroll
                for (int d = 0; d < 4; d++)
                    o[i][d] += p[i] * v[d];
        }
        __syncthreads();
    }

    #pragma unroll
    for (int i = 0; i < 4; i++) {
        float inv = 1.f / run_sum[i];
        size_t row = (size_t)b * NN + seg_start + q0 + ty * 4 + i;
        #pragma unroll
        for (int d = 0; d < 4; d++)
            ctx[row * HH + h * DH + tx * 4 + d] = o[i][d] * inv;
    }
}

// ---------------------------------------------------------------------------
// y = LayerNorm(x + r) * g + b   (last dim 256, one block per row)
// ---------------------------------------------------------------------------
__global__ void add_ln_kernel(const float* __restrict__ x,
                              const float* __restrict__ r,
                              const float* __restrict__ g,
                              const float* __restrict__ bta,
                              float* __restrict__ y)
{
    const size_t row = blockIdx.x;
    const int t = threadIdx.x;   // 256
    __shared__ float red[256];

    float v = x[row * HH + t] + r[row * HH + t];
    red[t] = v;
    __syncthreads();
    #pragma unroll
    for (int o = 128; o; o >>= 1) { if (t < o) red[t] += red[t + o]; __syncthreads(); }
    float mu = red[0] * (1.f / HH);
    __syncthreads();
    float d = v - mu;
    red[t] = d * d;
    __syncthreads();
    #pragma unroll
    for (int o = 128; o; o >>= 1) { if (t < o) red[t] += red[t + o]; __syncthreads(); }
    float var = red[0] * (1.f / HH);
    y[row * HH + t] = d * rsqrtf(var + 1e-5f) * g[t] + bta[t];
}

// ---------------------------------------------------------------------------
// Per-segment mean over rows
// ---------------------------------------------------------------------------
__global__ void seg_mean_kernel(const float* __restrict__ y,
                                float* __restrict__ means)
{
    const int b = blockIdx.x / 3, seg = blockIdx.x % 3;
    const int start = (seg == 0) ? 0 : (seg == 1 ? NACC : NACC + NREJ);
    const int S = (seg == 0) ? NACC : NREJ;
    const int t = threadIdx.x;           // 256 threads = one per column
    float s0 = 0.f, s1 = 0.f, s2 = 0.f, s3 = 0.f;
    for (int i = 0; i < S; i += 4) {
        s0 += y[((size_t)b * NN + start + i + 0) * HH + t];
        s1 += y[((size_t)b * NN + start + i + 1) * HH + t];
        s2 += y[((size_t)b * NN + start + i + 2) * HH + t];
        s3 += y[((size_t)b * NN + start + i + 3) * HH + t];
    }
    means[(size_t)blockIdx.x * HH + t] = (s0 + s1 + s2 + s3) * (1.f / S);
}

// ---------------------------------------------------------------------------
// out[b,:] = relu( (m_p - m_n + m_f) @ W + bias )
// ---------------------------------------------------------------------------
__global__ void final_kernel(const float* __restrict__ means,
                             const float* __restrict__ W,
                             const float* __restrict__ bias,
                             float* __restrict__ out)
{
    const int b = blockIdx.x, t = threadIdx.x;
    __shared__ float d[256];
    d[t] = means[(b * 3 + 0) * HH + t]
         - means[(b * 3 + 1) * HH + t]
         + means[(b * 3 + 2) * HH + t];
    __syncthreads();
    float acc = bias[t];
    for (int k = 0; k < HH; k++)
        acc = fmaf(d[k], W[(size_t)k * HH + t], acc);
    out[(size_t)b * HH + t] = fmaxf(acc, 0.f);
}

// ---------------------------------------------------------------------------
// Orchestration
// ---------------------------------------------------------------------------
static inline void launch_gemm(const float* A, const float* B, const float* bias,
                               float* C, int M, int N, int K,
                               size_t sA, size_t sB, size_t sC, int batch, int relu)
{
    dim3 grid((N + 63) / 64, (M + 63) / 64, batch);
    dim3 block(16, 16);
    gemm_bias_kernel<<<grid, block>>>(A, B, bias, C, M, N, K, sA, sB, sC, relu);
}

extern "C" void kernel_launch(void* const* d_in, const int* in_sizes, int n_in,
                              void* d_out, int out_size)
{
    const int*   hyperneigh = (const int*)  d_in[0];
    const float* HT         = (const float*)d_in[1];
    const float* emb        = (const float*)d_in[2];
    const float* Wg1        = (const float*)d_in[3];
    const float* bg1        = (const float*)d_in[4];
    const float* Wg2        = (const float*)d_in[5];
    const float* bg2        = (const float*)d_in[6];
    const float* Wqkv       = (const float*)d_in[7];
    const float* bqkv       = (const float*)d_in[8];
    const float* Wo         = (const float*)d_in[9];
    const float* bo         = (const float*)d_in[10];
    const float* ln1_g      = (const float*)d_in[11];
    const float* ln1_b      = (const float*)d_in[12];
    const float* Wff1       = (const float*)d_in[13];
    const float* bff1       = (const float*)d_in[14];
    const float* Wff2       = (const float*)d_in[15];
    const float* bff2       = (const float*)d_in[16];
    const float* ln2_g      = (const float*)d_in[17];
    const float* ln2_b      = (const float*)d_in[18];
    const float* fc1_W      = (const float*)d_in[19];
    const float* fc1_b      = (const float*)d_in[20];
    float* out = (float*)d_out;

    float *bufA, *bufB, *bufT, *qkv, *ff, *means;
    cudaGetSymbolAddress((void**)&bufA,  g_bufA);
    cudaGetSymbolAddress((void**)&bufB,  g_bufB);
    cudaGetSymbolAddress((void**)&bufT,  g_bufT);
    cudaGetSymbolAddress((void**)&qkv,   g_qkv);
    cudaGetSymbolAddress((void**)&ff,    g_ff);
    cudaGetSymbolAddress((void**)&means, g_means);
    float* ctx = ff;   // disjoint live ranges

    const int ROWS = BB * NN;               // 16384
    const size_t sBNH = (size_t)NN * HH;    // per-batch stride for (N,H)
    const size_t sHT  = (size_t)NN * NN;

    // 1. gather
    {
        size_t total = (size_t)ROWS * (HH / 4);
        gather_kernel<<<(unsigned)((total + 255) / 256), 256>>>(hyperneigh, emb, bufA);
    }

    // 2. T = A @ Wg1
    launch_gemm(bufA, Wg1, nullptr, bufT, ROWS, HH, HH, 0, 0, 0, 1, 0);
    // 3. B = HT @ T + bg1   (batched over 16)
    launch_gemm(HT, bufT, bg1, bufB, NN, HH, NN, sHT, sBNH, sBNH, BB, 0);
    // 4. T = B @ Wg2
    launch_gemm(bufB, Wg2, nullptr, bufT, ROWS, HH, HH, 0, 0, 0, 1, 0);
    // 5. A = HT @ T + bg2  -> h2
    launch_gemm(HT, bufT, bg2, bufA, NN, HH, NN, sHT, sBNH, sBNH, BB, 0);

    // 6. qkv = A @ Wqkv + bqkv
    launch_gemm(bufA, Wqkv, bqkv, qkv, ROWS, 3 * HH, HH, 0, 0, 0, 1, 0);

    // 7. attention per segment (block-diagonal), static 48KB smem
    attn_kernel<<<dim3(NACC / 64, NH, BB), dim3(16, 16)>>>(qkv, ctx, 0, NACC);
    attn_kernel<<<dim3(NREJ / 64, NH, BB), dim3(16, 16)>>>(qkv, ctx, NACC, NREJ);
    attn_kernel<<<dim3(NFRD / 64, NH, BB), dim3(16, 16)>>>(qkv, ctx, NACC + NREJ, NFRD);

    // 8. T = ctx @ Wo + bo
    launch_gemm(ctx, Wo, bo, bufT, ROWS, HH, HH, 0, 0, 0, 1, 0);
    // 9. B = LN(A + T; ln1)
    add_ln_kernel<<<ROWS, HH>>>(bufA, bufT, ln1_g, ln1_b, bufB);
    // 10. ff = relu(B @ Wff1 + bff1)   (overwrites ctx, which is dead)
    launch_gemm(bufB, Wff1, bff1, ff, ROWS, FF, HH, 0, 0, 0, 1, 1);
    // 11. T = ff @ Wff2 + bff2
    launch_gemm(ff, Wff2, bff2, bufT, ROWS, HH, FF, 0, 0, 0, 1, 0);
    // 12. A = LN(B + T; ln2)
    add_ln_kernel<<<ROWS, HH>>>(bufB, bufT, ln2_g, ln2_b, bufA);

    // 13. segment means
    seg_mean_kernel<<<BB * 3, HH>>>(bufA, means);
    // 14. out = relu((m_p - m_n + m_f) @ fc1_W + fc1_b)
    final_kernel<<<BB, HH>>>(means, fc1_W, fc1_b, out);

    (void)in_sizes; (void)n_in; (void)out_size;
}

// round 4
// speedup vs baseline: 2.4479x; 2.4479x over previous
#include <cuda_runtime.h>
#include <cuda_bf16.h>
#include <math.h>
#include <stdint.h>

// ---------------------------------------------------------------------------
// Problem constants (fixed by dataset)
// ---------------------------------------------------------------------------
#define BB   16
#define NN   1024
#define HH   256
#define FF   400
#define NH   4
#define DH   64
#define NACC 512
#define NREJ 256
#define NFRD 256

// ---------------------------------------------------------------------------
// Static scratch (no allocation allowed). ~127 MB total.
// g_ff doubles as ctx storage (live ranges disjoint; FF >= HH).
// ---------------------------------------------------------------------------
__device__ float g_bufA[BB * NN * HH];
__device__ float g_bufB[BB * NN * HH];
__device__ float g_bufT[BB * NN * HH];
__device__ float g_qkv [BB * NN * 3 * HH];
__device__ float g_ff  [BB * NN * FF];
__device__ float g_means[BB * 3 * HH];

// ---------------------------------------------------------------------------
// Gather: h0[b,n,:] = emb_table[idx[b,n], :]   (vectorized float4)
// ---------------------------------------------------------------------------
__global__ void gather_kernel(const int* __restrict__ idx,
                              const float* __restrict__ table,
                              float* __restrict__ out)
{
    size_t i = (size_t)blockIdx.x * blockDim.x + threadIdx.x;
    if (i >= (size_t)BB * NN * (HH / 4)) return;
    size_t row = i >> 6;
    int    e4  = (int)(i & 63);
    int    id  = idx[row];
    reinterpret_cast<float4*>(out)[row * 64 + e4] =
        reinterpret_cast<const float4*>(table)[(size_t)id * 64 + e4];
}

// ---------------------------------------------------------------------------
// tf32 tensor-core batched GEMM:
//   C[z] = A[z] (MxK) @ B[z] (KxN) [+ bias] [relu], all row-major fp32.
// Block: 128x128 C tile, 256 threads = 8 warps (2 x 4), warp tile m64 x n32.
// K-tile 32, single-buffered smem. mma.sync m16n8k8 tf32.
// Requirements: M % 128 == 0, K % 4 == 0, N % 4 == 0 (all hold here).
// ---------------------------------------------------------------------------
__device__ __forceinline__ uint32_t f2tf32(float f)
{
    uint32_t u;
    asm("cvt.rna.tf32.f32 %0, %1;" : "=r"(u) : "f"(f));
    return u;
}

#define SA_STRIDE 36   // 32 + 4 pad: frag banks = 4*g + tg (conflict-free)
#define SB_STRIDE 132  // 128 + 4 pad: frag banks = 4*tg + g (conflict-free)

__global__ __launch_bounds__(256)
void gemm_tf32_kernel(const float* __restrict__ A,
                      const float* __restrict__ B,
                      const float* __restrict__ bias,
                      float* __restrict__ C,
                      int M, int N, int K,
                      size_t strideA, size_t strideB, size_t strideC,
                      int relu)
{
    A += (size_t)blockIdx.z * strideA;
    B += (size_t)blockIdx.z * strideB;
    C += (size_t)blockIdx.z * strideC;

    __shared__ uint32_t sA[128 * SA_STRIDE];   // [m][k] tf32 bits
    __shared__ uint32_t sB[32 * SB_STRIDE];    // [k][n] tf32 bits

    const int tid  = threadIdx.x;
    const int warp = tid >> 5, lane = tid & 31;
    const int wm = warp & 1;        // 0..1 -> 64 rows each
    const int wn = warp >> 1;       // 0..3 -> 32 cols each
    const int g  = lane >> 2;       // groupID 0..7
    const int tg = lane & 3;        // thread-in-group 0..3

    const int m0 = blockIdx.y * 128;
    const int n0 = blockIdx.x * 128;

    float acc[4][4][4];             // [mi][ni][c-reg]
    #pragma unroll
    for (int mi = 0; mi < 4; mi++)
        #pragma unroll
        for (int ni = 0; ni < 4; ni++)
            #pragma unroll
            for (int c = 0; c < 4; c++) acc[mi][ni][c] = 0.f;

    for (int k0 = 0; k0 < K; k0 += 32) {
        // --- load A tile 128x32: 1024 float4, 4 per thread ---
        #pragma unroll
        for (int r = 0; r < 4; r++) {
            int idx = r * 256 + tid;
            int m = idx >> 3, k4 = idx & 7;
            int kg = k0 + k4 * 4;
            float4 v = make_float4(0.f, 0.f, 0.f, 0.f);
            if (kg < K)
                v = *reinterpret_cast<const float4*>(&A[(size_t)(m0 + m) * K + kg]);
            uint4 u = make_uint4(f2tf32(v.x), f2tf32(v.y), f2tf32(v.z), f2tf32(v.w));
            *reinterpret_cast<uint4*>(&sA[m * SA_STRIDE + k4 * 4]) = u;
        }
        // --- load B tile 32x128: 1024 float4, 4 per thread ---
        #pragma unroll
        for (int r = 0; r < 4; r++) {
            int idx = r * 256 + tid;
            int k = idx >> 5, n4 = idx & 31;
            int ng = n0 + n4 * 4;
            float4 v = make_float4(0.f, 0.f, 0.f, 0.f);
            if (k0 + k < K && ng < N)
                v = *reinterpret_cast<const float4*>(&B[(size_t)(k0 + k) * N + ng]);
            uint4 u = make_uint4(f2tf32(v.x), f2tf32(v.y), f2tf32(v.z), f2tf32(v.w));
            *reinterpret_cast<uint4*>(&sB[k * SB_STRIDE + n4 * 4]) = u;
        }
        __syncthreads();

        // --- 4 x k8 mma steps ---
        #pragma unroll
        for (int kk = 0; kk < 4; kk++) {
            const int kb = kk * 8;
            uint32_t af[4][4];
            #pragma unroll
            for (int mi = 0; mi < 4; mi++) {
                int row = wm * 64 + mi * 16 + g;
                af[mi][0] = sA[row * SA_STRIDE + kb + tg];
                af[mi][1] = sA[(row + 8) * SA_STRIDE + kb + tg];
                af[mi][2] = sA[row * SA_STRIDE + kb + tg + 4];
                af[mi][3] = sA[(row + 8) * SA_STRIDE + kb + tg + 4];
            }
            uint32_t bf[4][2];
            #pragma unroll
            for (int ni = 0; ni < 4; ni++) {
                int col = wn * 32 + ni * 8 + g;
                bf[ni][0] = sB[(kb + tg) * SB_STRIDE + col];
                bf[ni][1] = sB[(kb + tg + 4) * SB_STRIDE + col];
            }
            #pragma unroll
            for (int mi = 0; mi < 4; mi++)
                #pragma unroll
                for (int ni = 0; ni < 4; ni++) {
                    asm volatile(
                        "mma.sync.aligned.m16n8k8.row.col.f32.tf32.tf32.f32 "
                        "{%0,%1,%2,%3}, {%4,%5,%6,%7}, {%8,%9}, {%0,%1,%2,%3};\n"
                        : "+f"(acc[mi][ni][0]), "+f"(acc[mi][ni][1]),
                          "+f"(acc[mi][ni][2]), "+f"(acc[mi][ni][3])
                        : "r"(af[mi][0]), "r"(af[mi][1]),
                          "r"(af[mi][2]), "r"(af[mi][3]),
                          "r"(bf[ni][0]), "r"(bf[ni][1]));
                }
        }
        __syncthreads();
    }

    // --- epilogue: c0/c1 at (row, col..col+1), c2/c3 at (row+8, ...) ---
    #pragma unroll
    for (int mi = 0; mi < 4; mi++) {
        int row = m0 + wm * 64 + mi * 16 + g;
        #pragma unroll
        for (int ni = 0; ni < 4; ni++) {
            int col = n0 + wn * 32 + ni * 8 + tg * 2;
            if (col >= N) continue;   // col even, N even -> col+1 < N too
            float b0 = bias ? bias[col]     : 0.f;
            float b1 = bias ? bias[col + 1] : 0.f;
            float v0 = acc[mi][ni][0] + b0;
            float v1 = acc[mi][ni][1] + b1;
            float v2 = acc[mi][ni][2] + b0;
            float v3 = acc[mi][ni][3] + b1;
            if (relu) {
                v0 = fmaxf(v0, 0.f); v1 = fmaxf(v1, 0.f);
                v2 = fmaxf(v2, 0.f); v3 = fmaxf(v3, 0.f);
            }
            *reinterpret_cast<float2*>(&C[(size_t)row * N + col]) =
                make_float2(v0, v1);
            *reinterpret_cast<float2*>(&C[(size_t)(row + 8) * N + col]) =
                make_float2(v2, v3);
        }
    }
}

// ---------------------------------------------------------------------------
// Flash-style attention for one block-diagonal segment (unchanged, fp32).
// ---------------------------------------------------------------------------
__global__ void attn_kernel(const float* __restrict__ qkv,
                            float* __restrict__ ctx,
                            int seg_start, int S)
{
    __shared__ float sQ [64 * 64];
    __shared__ float sKP[64 * 64];
    __shared__ float sV [64 * 64];

    const int h  = blockIdx.y;
    const int b  = blockIdx.z;
    const int q0 = blockIdx.x * 64;
    const int tx = threadIdx.x, ty = threadIdx.y;
    const int tid = ty * 16 + tx;

    const size_t rowbase = ((size_t)b * NN + seg_start) * (3 * HH);

    #pragma unroll
    for (int r = 0; r < 4; r++) {
        int idx = r * 256 + tid;
        int i = idx >> 4, d4 = idx & 15;
        float4 v = *reinterpret_cast<const float4*>(
            &qkv[rowbase + (size_t)(q0 + i) * (3 * HH) + h * DH + d4 * 4]);
        *reinterpret_cast<float4*>(&sQ[i * 64 + d4 * 4]) = v;
    }

    float run_max[4], run_sum[4], o[4][4];
    #pragma unroll
    for (int i = 0; i < 4; i++) {
        run_max[i] = -1e30f; run_sum[i] = 0.f;
        #pragma unroll
        for (int d = 0; d < 4; d++) o[i][d] = 0.f;
    }

    __syncthreads();

    for (int kt = 0; kt < S; kt += 64) {
        #pragma unroll
        for (int r = 0; r < 4; r++) {
            int idx = r * 256 + tid;
            int j = idx >> 4, d4 = idx & 15;
            float4 v = *reinterpret_cast<const float4*>(
                &qkv[rowbase + (size_t)(kt + j) * (3 * HH) + HH + h * DH + d4 * 4]);
            int d0 = d4 * 4;
            sKP[(d0 + 0) * 64 + (j ^ (d0 + 0))] = v.x;
            sKP[(d0 + 1) * 64 + (j ^ (d0 + 1))] = v.y;
            sKP[(d0 + 2) * 64 + (j ^ (d0 + 2))] = v.z;
            sKP[(d0 + 3) * 64 + (j ^ (d0 + 3))] = v.w;
        }
        __syncthreads();

        float acc[4][4] = {};
        #pragma unroll 4
        for (int dd = 0; dd < 16; dd++) {
            float4 a4[4];
            #pragma unroll
            for (int i = 0; i < 4; i++)
                a4[i] = *reinterpret_cast<const float4*>(
                    &sQ[(ty * 4 + i) * 64 + dd * 4]);
            #pragma unroll
            for (int c = 0; c < 4; c++) {
                const int d = dd * 4 + c;
                float4 b4 = *reinterpret_cast<const float4*>(
                    &sKP[d * 64 + ((tx * 4) ^ (d & 60))]);
                float bv[4];
                ((float*)&bv)[0 ^ c] = b4.x;
                ((float*)&bv)[1 ^ c] = b4.y;
                ((float*)&bv)[2 ^ c] = b4.z;
                ((float*)&bv)[3 ^ c] = b4.w;
                float av[4] = { ((const float*)&a4[0])[c],
                                ((const float*)&a4[1])[c],
                                ((const float*)&a4[2])[c],
                                ((const float*)&a4[3])[c] };
                #pragma unroll
                for (int i = 0; i < 4; i++)
                    #pragma unroll
                    for (int j = 0; j < 4; j++)
                        acc[i][j] += av[i] * bv[j];
            }
        }
        __syncthreads();

        #pragma unroll
        for (int i = 0; i < 4; i++) {
            float tmax = -1e30f;
            #pragma unroll
            for (int j = 0; j < 4; j++) {
                acc[i][j] *= 0.125f;
                tmax = fmaxf(tmax, acc[i][j]);
            }
            #pragma unroll
            for (int off = 8; off; off >>= 1)
                tmax = fmaxf(tmax, __shfl_xor_sync(0xffffffffu, tmax, off, 16));
            float nm = fmaxf(run_max[i], tmax);
            float f  = __expf(run_max[i] - nm);
            float ts = 0.f;
            #pragma unroll
            for (int j = 0; j < 4; j++) {
                acc[i][j] = __expf(acc[i][j] - nm);
                ts += acc[i][j];
            }
            #pragma unroll
            for (int off = 8; off; off >>= 1)
                ts += __shfl_xor_sync(0xffffffffu, ts, off, 16);
            run_sum[i] = run_sum[i] * f + ts;
            run_max[i] = nm;
            #pragma unroll
            for (int d = 0; d < 4; d++) o[i][d] *= f;
            #pragma unroll
            for (int j = 0; j < 4; j++)
                sKP[(ty * 4 + i) * 64 + tx * 4 + j] = acc[i][j];
        }

        #pragma unroll
        for (int r = 0; r < 4; r++) {
            int idx = r * 256 + tid;
            int j = idx >> 4, d4 = idx & 15;
            float4 v = *reinterpret_cast<const float4*>(
                &qkv[rowbase + (size_t)(kt + j) * (3 * HH) + 2 * HH + h * DH + d4 * 4]);
            *reinterpret_cast<float4*>(&sV[j * 64 + d4 * 4]) = v;
        }
        __syncthreads();

        #pragma unroll 4
        for (int j = 0; j < 64; j++) {
            float p[4];
            #pragma unroll
            for (int i = 0; i < 4; i++) p[i] = sKP[(ty * 4 + i) * 64 + j];
            float4 v4 = *reinterpret_cast<const float4*>(&sV[j * 64 + tx * 4]);
            const float* v = (const float*)&v4;
            #pragma unroll
            for (int i = 0; i < 4; i++)
                #pragma unroll
                for (int d = 0; d < 4; d++)
                    o[i][d] += p[i] * v[d];
        }
        __syncthreads();
    }

    #pragma unroll
    for (int i = 0; i < 4; i++) {
        float inv = 1.f / run_sum[i];
        size_t row = (size_t)b * NN + seg_start + q0 + ty * 4 + i;
        #pragma unroll
        for (int d = 0; d < 4; d++)
            ctx[row * HH + h * DH + tx * 4 + d] = o[i][d] * inv;
    }
}

// ---------------------------------------------------------------------------
// y = LayerNorm(x + r) * g + b   (last dim 256, one block per row)
// ---------------------------------------------------------------------------
__global__ void add_ln_kernel(const float* __restrict__ x,
                              const float* __restrict__ r,
                              const float* __restrict__ g,
                              const float* __restrict__ bta,
                              float* __restrict__ y)
{
    const size_t row = blockIdx.x;
    const int t = threadIdx.x;
    __shared__ float red[256];

    float v = x[row * HH + t] + r[row * HH + t];
    red[t] = v;
    __syncthreads();
    #pragma unroll
    for (int o = 128; o; o >>= 1) { if (t < o) red[t] += red[t + o]; __syncthreads(); }
    float mu = red[0] * (1.f / HH);
    __syncthreads();
    float d = v - mu;
    red[t] = d * d;
    __syncthreads();
    #pragma unroll
    for (int o = 128; o; o >>= 1) { if (t < o) red[t] += red[t + o]; __syncthreads(); }
    float var = red[0] * (1.f / HH);
    y[row * HH + t] = d * rsqrtf(var + 1e-5f) * g[t] + bta[t];
}

// ---------------------------------------------------------------------------
// Per-segment mean over rows
// ---------------------------------------------------------------------------
__global__ void seg_mean_kernel(const float* __restrict__ y,
                                float* __restrict__ means)
{
    const int b = blockIdx.x / 3, seg = blockIdx.x % 3;
    const int start = (seg == 0) ? 0 : (seg == 1 ? NACC : NACC + NREJ);
    const int S = (seg == 0) ? NACC : NREJ;
    const int t = threadIdx.x;
    float s0 = 0.f, s1 = 0.f, s2 = 0.f, s3 = 0.f;
    for (int i = 0; i < S; i += 4) {
        s0 += y[((size_t)b * NN + start + i + 0) * HH + t];
        s1 += y[((size_t)b * NN + start + i + 1) * HH + t];
        s2 += y[((size_t)b * NN + start + i + 2) * HH + t];
        s3 += y[((size_t)b * NN + start + i + 3) * HH + t];
    }
    means[(size_t)blockIdx.x * HH + t] = (s0 + s1 + s2 + s3) * (1.f / S);
}

// ---------------------------------------------------------------------------
// out[b,:] = relu( (m_p - m_n + m_f) @ W + bias )
// ---------------------------------------------------------------------------
__global__ void final_kernel(const float* __restrict__ means,
                             const float* __restrict__ W,
                             const float* __restrict__ bias,
                             float* __restrict__ out)
{
    const int b = blockIdx.x, t = threadIdx.x;
    __shared__ float d[256];
    d[t] = means[(b * 3 + 0) * HH + t]
         - means[(b * 3 + 1) * HH + t]
         + means[(b * 3 + 2) * HH + t];
    __syncthreads();
    float acc = bias[t];
    for (int k = 0; k < HH; k++)
        acc = fmaf(d[k], W[(size_t)k * HH + t], acc);
    out[(size_t)b * HH + t] = fmaxf(acc, 0.f);
}

// ---------------------------------------------------------------------------
// Orchestration
// ---------------------------------------------------------------------------
static inline void launch_gemm(const float* A, const float* B, const float* bias,
                               float* C, int M, int N, int K,
                               size_t sA, size_t sB, size_t sC, int batch, int relu)
{
    dim3 grid((N + 127) / 128, M / 128, batch);
    gemm_tf32_kernel<<<grid, 256>>>(A, B, bias, C, M, N, K, sA, sB, sC, relu);
}

extern "C" void kernel_launch(void* const* d_in, const int* in_sizes, int n_in,
                              void* d_out, int out_size)
{
    const int*   hyperneigh = (const int*)  d_in[0];
    const float* HT         = (const float*)d_in[1];
    const float* emb        = (const float*)d_in[2];
    const float* Wg1        = (const float*)d_in[3];
    const float* bg1        = (const float*)d_in[4];
    const float* Wg2        = (const float*)d_in[5];
    const float* bg2        = (const float*)d_in[6];
    const float* Wqkv       = (const float*)d_in[7];
    const float* bqkv       = (const float*)d_in[8];
    const float* Wo         = (const float*)d_in[9];
    const float* bo         = (const float*)d_in[10];
    const float* ln1_g      = (const float*)d_in[11];
    const float* ln1_b      = (const float*)d_in[12];
    const float* Wff1       = (const float*)d_in[13];
    const float* bff1       = (const float*)d_in[14];
    const float* Wff2       = (const float*)d_in[15];
    const float* bff2       = (const float*)d_in[16];
    const float* ln2_g      = (const float*)d_in[17];
    const float* ln2_b      = (const float*)d_in[18];
    const float* fc1_W      = (const float*)d_in[19];
    const float* fc1_b      = (const float*)d_in[20];
    float* out = (float*)d_out;

    float *bufA, *bufB, *bufT, *qkv, *ff, *means;
    cudaGetSymbolAddress((void**)&bufA,  g_bufA);
    cudaGetSymbolAddress((void**)&bufB,  g_bufB);
    cudaGetSymbolAddress((void**)&bufT,  g_bufT);
    cudaGetSymbolAddress((void**)&qkv,   g_qkv);
    cudaGetSymbolAddress((void**)&ff,    g_ff);
    cudaGetSymbolAddress((void**)&means, g_means);
    float* ctx = ff;   // disjoint live ranges

    const int ROWS = BB * NN;
    const size_t sBNH = (size_t)NN * HH;
    const size_t sHT  = (size_t)NN * NN;

    // 1. gather
    {
        size_t total = (size_t)ROWS * (HH / 4);
        gather_kernel<<<(unsigned)((total + 255) / 256), 256>>>(hyperneigh, emb, bufA);
    }

    // 2. T = A @ Wg1
    launch_gemm(bufA, Wg1, nullptr, bufT, ROWS, HH, HH, 0, 0, 0, 1, 0);
    // 3. B = HT @ T + bg1   (batched over 16)
    launch_gemm(HT, bufT, bg1, bufB, NN, HH, NN, sHT, sBNH, sBNH, BB, 0);
    // 4. T = B @ Wg2
    launch_gemm(bufB, Wg2, nullptr, bufT, ROWS, HH, HH, 0, 0, 0, 1, 0);
    // 5. A = HT @ T + bg2  -> h2
    launch_gemm(HT, bufT, bg2, bufA, NN, HH, NN, sHT, sBNH, sBNH, BB, 0);

    // 6. qkv = A @ Wqkv + bqkv
    launch_gemm(bufA, Wqkv, bqkv, qkv, ROWS, 3 * HH, HH, 0, 0, 0, 1, 0);

    // 7. attention per segment (block-diagonal), static 48KB smem
    attn_kernel<<<dim3(NACC / 64, NH, BB), dim3(16, 16)>>>(qkv, ctx, 0, NACC);
    attn_kernel<<<dim3(NREJ / 64, NH, BB), dim3(16, 16)>>>(qkv, ctx, NACC, NREJ);
    attn_kernel<<<dim3(NFRD / 64, NH, BB), dim3(16, 16)>>>(qkv, ctx, NACC + NREJ, NFRD);

    // 8. T = ctx @ Wo + bo
    launch_gemm(ctx, Wo, bo, bufT, ROWS, HH, HH, 0, 0, 0, 1, 0);
    // 9. B = LN(A + T; ln1)
    add_ln_kernel<<<ROWS, HH>>>(bufA, bufT, ln1_g, ln1_b, bufB);
    // 10. ff = relu(B @ Wff1 + bff1)   (overwrites ctx, which is dead)
    launch_gemm(bufB, Wff1, bff1, ff, ROWS, FF, HH, 0, 0, 0, 1, 1);
    // 11. T = ff @ Wff2 + bff2
    launch_gemm(ff, Wff2, bff2, bufT, ROWS, HH, FF, 0, 0, 0, 1, 0);
    // 12. A = LN(B + T; ln2)
    add_ln_kernel<<<ROWS, HH>>>(bufB, bufT, ln2_g, ln2_b, bufA);

    // 13. segment means
    seg_mean_kernel<<<BB * 3, HH>>>(bufA, means);
    // 14. out = relu((m_p - m_n + m_f) @ fc1_W + fc1_b)
    final_kernel<<<BB, HH>>>(means, fc1_W, fc1_b, out);

    (void)in_sizes; (void)n_in; (void)out_size;
}